// round 6
// baseline (speedup 1.0000x reference)
#include <cuda_runtime.h>
#include <math.h>
#include <float.h>

#define BB 1024
#define TT 512
#define KK 48
#define NEGV (-10000.0f)
#define TAG_START 46
#define TAG_STOP 47
#define NB 4                        // batches per CTA
#define MAIN_THREADS (NB * 96)      // 384: (batch, next, half)

// ---- device scratch (no allocations allowed) ----
__device__ int   g_bestlast[BB];
__device__ float g_v[BB * TT * KK];   // loop-top Viterbi value vectors (100 MB)
__device__ float g_u[BB * TT * KK];   // per-step pre-emit max values   (100 MB)

// f32x2 packed helpers (sm_103a; ptxas never auto-fuses these)
#define F32X2_FMA(d, a, b, c) \
    asm("fma.rn.f32x2 %0, %1, %2, %3;" : "=l"(d) : "l"(a), "l"(b), "l"(c))
#define F32X2_ADD(d, a, b) \
    asm("add.rn.f32x2 %0, %1, %2;" : "=l"(d) : "l"(a), "l"(b))
#define F32X2_UNPACK(lo, hi, x) \
    asm("mov.b64 {%0, %1}, %2;" : "=f"(lo), "=f"(hi) : "l"(x))
#define F32X2_PACK(d, lo, hi) \
    asm("mov.b64 %0, {%1, %2};" : "=l"(d) : "f"(lo), "f"(hi))

// ============================================================
// Fused kernel: forward (E-domain, log/exp OFF the recurrence chain)
// + Viterbi max recurrence + gold score.
// tid = g*96 + nx*2 + h : g=local batch, nx=next tag, h=prev half.
// Forward state: E_n = exp(alpha_n - m). Step:
//   acc_n = sum_p E_p * M[n,p];  E'_n = acc_n * f,  f = expf(emit_n - 12)
// f depends only on the (prefetched) emission -> computed one step ahead,
// completely off the serial chain. m += 12/step; every 4th step fold 1/mx
// into next f and accumulate log(mx) (off-chain).
// Viterbi: v' = max_p(v_p + t[n,p]) + emit (exact reference fp ops); the
// pre-emit max (u) is stored per step so backtrack can equality-match the
// argmax (bit-exact first-max).
// ============================================================
__global__ void __launch_bounds__(MAIN_THREADS)
crf_main_kernel(const float* __restrict__ feats,
                const float* __restrict__ trans,
                const int* __restrict__ tags,
                float* __restrict__ out) {
    __shared__ float trans_sh[KK * 49];                 // masked, pitch 49
    __shared__ __align__(16) float e_sh[2][NB][KK];     // double buffered (E)
    __shared__ __align__(16) float v_sh[2][NB][KK];
    __shared__ int tag_sh[NB][TT];

    int tid = threadIdx.x;
    int g   = tid / 96;          // group = 3 aligned warps
    int r   = tid - g * 96;
    int nx  = r >> 1;
    int h   = r & 1;
    int base = h * 24;
    int b   = blockIdx.x * NB + g;
    int barid = g + 1;           // named barrier per group

    for (int i = tid; i < KK * KK; i += MAIN_THREADS) {
        int rr = i / KK, cc = i - rr * KK;
        float tv = trans[i];
        if (rr == TAG_START || cc == TAG_STOP) tv = NEGV;
        trans_sh[rr * 49 + cc] = tv;
    }
    for (int i = tid; i < NB * TT; i += MAIN_THREADS)
        ((int*)tag_sh)[i] = tags[(size_t)blockIdx.x * NB * TT + i];
    __syncthreads();

    // packed register slices of this next-row (24 prevs -> 12 f32x2)
    unsigned long long Ms2[12], ts2[12];
#pragma unroll
    for (int j = 0; j < 12; j++) {
        float t0 = trans_sh[nx * 49 + base + 2 * j];
        float t1 = trans_sh[nx * 49 + base + 2 * j + 1];
        float M0 = (t0 <= -9000.f) ? 0.f : __expf(t0);
        float M1 = (t1 <= -9000.f) ? 0.f : __expf(t1);
        F32X2_PACK(ts2[j], t0, t1);
        F32X2_PACK(Ms2[j], M0, M1);
    }

    float E = (nx == TAG_START) ? 1.f : 0.f;   // exp(alpha - m), m = 0
    float v = (nx == TAG_START) ? 0.f : NEGV;
    float sum_log = 0.f;     // sum of log(mx) renorm corrections
    float gold = 0.f;
    int prevtag = TAG_START;

    const float* fp = feats + (size_t)b * TT * KK + nx;
    float emit_cur = fp[0];
    float f_cur = __expf(emit_cur - 12.f);
    float* vout = g_v + (size_t)b * TT * KK + nx;
    float* uout = g_u + (size_t)b * TT * KK + nx;

    for (int t = 0; t < TT; t++) {
        int par = t & 1;
        float emit_nxt = (t + 1 < TT) ? fp[(size_t)(t + 1) * KK] : 0.f;

        if (h == 0) {
            e_sh[par][g][nx] = E;
            v_sh[par][g][nx] = v;
            vout[(size_t)t * KK] = v;     // loop-top value vector (v_{t-1})
        }
        asm volatile("bar.sync %0, 96;" :: "r"(barid));

        int tagt = tag_sh[g][t];
        if (h == 0 && nx == tagt)
            gold += emit_cur + trans_sh[tagt * 49 + prevtag];
        prevtag = tagt;

        const ulonglong2* ep = (const ulonglong2*)&e_sh[par][g][base];
        const ulonglong2* vp = (const ulonglong2*)&v_sh[par][g][base];
        unsigned long long acc0 = 0ull, acc1 = 0ull;
        float b0 = -FLT_MAX, b1 = -FLT_MAX;
#pragma unroll
        for (int j = 0; j < 6; j++) {
            ulonglong2 e2 = ep[j];
            ulonglong2 v2 = vp[j];
            F32X2_FMA(acc0, e2.x, Ms2[2 * j], acc0);
            F32X2_FMA(acc1, e2.y, Ms2[2 * j + 1], acc1);
            unsigned long long s01, s23;
            F32X2_ADD(s01, v2.x, ts2[2 * j]);
            F32X2_ADD(s23, v2.y, ts2[2 * j + 1]);
            float s0, s1, s2, s3;
            F32X2_UNPACK(s0, s1, s01);
            F32X2_UNPACK(s2, s3, s23);
            b0 = fmaxf(b0, s0); b1 = fmaxf(b1, s1);
            b0 = fmaxf(b0, s2); b1 = fmaxf(b1, s3);
        }
        float a0, a1, a2, a3;
        F32X2_UNPACK(a0, a1, acc0);
        F32X2_UNPACK(a2, a3, acc1);
        float acc = (a0 + a1) + (a2 + a3);
        float best = fmaxf(b0, b1);
        acc += __shfl_xor_sync(0xFFFFFFFFu, acc, 1);
        best = fmaxf(best, __shfl_xor_sync(0xFFFFFFFFu, best, 1));

        if (h == 1) uout[(size_t)t * KK] = best;   // u_t (pre-emit max)

        E = acc * f_cur;               // short chain: FMA-tree -> shfl -> FMUL
        v = best + emit_cur;

        emit_cur = emit_nxt;
        float fn = __expf(emit_cur - 12.f);   // next step's factor (off-chain)
        if ((t & 3) == 3 && t != TT - 1) {
            // renorm: mx = max of loop-top E (e_sh[par] still valid: its next
            // overwrite at step t+2 is gated behind step t+1's barrier).
            float mx = -FLT_MAX;
#pragma unroll
            for (int p0 = 0; p0 < KK; p0 += 4) {
                float4 e4 = *reinterpret_cast<const float4*>(&e_sh[par][g][p0]);
                mx = fmaxf(mx, fmaxf(fmaxf(e4.x, e4.y), fmaxf(e4.z, e4.w)));
            }
            fn *= __fdividef(1.f, mx);
            sum_log += __logf(mx);
        }
        f_cur = fn;
    }

    // ---- epilogue ----
    float m_tot = 12.f * (float)TT + sum_log;
    asm volatile("bar.sync %0, 96;" :: "r"(barid));
    if (h == 0) {
        float tstop = trans_sh[TAG_STOP * 49 + nx];
        e_sh[0][g][nx] = E * __expf(tstop);        // term for logZ
        v_sh[0][g][nx] = v + tstop;
        e_sh[1][g][nx] = gold;
    }
    asm volatile("bar.sync %0, 96;" :: "r"(barid));
    if (r == 0) {
        float s = 0.f;
        for (int k = 0; k < KK; k++) s += e_sh[0][g][k];
        float logZ = m_tot + __logf(s);

        float gsum = 0.f;
        for (int k = 0; k < KK; k++) gsum += e_sh[1][g][k];
        gsum += trans_sh[TAG_STOP * 49 + tag_sh[g][TT - 1]];
        out[b] = logZ - gsum;                      // nll

        float bv = -FLT_MAX;
        int bi = 0;
        for (int k = 0; k < KK; k++) {
            float tv = v_sh[0][g][k];
            if (tv > bv) { bv = tv; bi = k; }      // first-max
        }
        out[BB + b] = bv;                          // path_score
        g_bestlast[b] = bi;
    }
}

// ============================================================
// Backtrack: one warp per batch. bp_t[cur] found by EQUALITY match:
// first p with v_t[p] + trans[cur,p] == u_t[cur]  (u_t = exact stored max;
// identical FADD rounding => bit-exact; first match == first argmax).
// No redux on the chain: shfl(target) || LDS(trans) -> FADD -> SETP ->
// ballot -> ffs  (~60 cyc/step). v/u rows prefetched 8-deep.
// ============================================================
__global__ void __launch_bounds__(256)
backtrack_kernel(const float* __restrict__ trans, float* __restrict__ out) {
    __shared__ float trans_sh[KK * 49];
    __shared__ float path_sh[8][TT];

    int tid = threadIdx.x;
    int w = tid >> 5, l = tid & 31;
    int b = blockIdx.x * 8 + w;

    for (int i = tid; i < KK * KK; i += 256) {
        int rr = i / KK, cc = i - rr * KK;
        float tv = trans[i];
        if (rr == TAG_START || cc == TAG_STOP) tv = NEGV;
        trans_sh[rr * 49 + cc] = tv;
    }
    __syncthreads();

    const float* vbase = g_v + (size_t)b * TT * KK;
    const float* ubase = g_u + (size_t)b * TT * KK;
    bool two = (l < 16);     // lanes 0..15 also own p = l+32

    float va[8], vb[8], ua[8], ub[8];
    float nva[8], nvb[8], nua[8], nub[8];
#pragma unroll
    for (int i = 0; i < 8; i++) {
        int t = 511 - i;
        va[i] = __ldg(&vbase[(size_t)t * KK + l]);
        ua[i] = __ldg(&ubase[(size_t)t * KK + l]);
        vb[i] = two ? __ldg(&vbase[(size_t)t * KK + l + 32]) : 0.f;
        ub[i] = two ? __ldg(&ubase[(size_t)t * KK + l + 32]) : 0.f;
        nvb[i] = 0.f; nub[i] = 0.f;
    }

    int cur = g_bestlast[b];

    for (int c = 0; c < 64; c++) {
        int tb = 511 - c * 8;
        if (c < 63) {
#pragma unroll
            for (int i = 0; i < 8; i++) {
                int t = tb - 8 - i;
                nva[i] = __ldg(&vbase[(size_t)t * KK + l]);
                nua[i] = __ldg(&ubase[(size_t)t * KK + l]);
                nvb[i] = two ? __ldg(&vbase[(size_t)t * KK + l + 32]) : 0.f;
                nub[i] = two ? __ldg(&ubase[(size_t)t * KK + l + 32]) : 0.f;
            }
        }
#pragma unroll
        for (int i = 0; i < 8; i++) {
            int t = tb - i;
            if (l == 0) path_sh[w][t] = (float)cur;
            // target = u_t[cur]  (cur is warp-uniform)
            float src = (cur < 32) ? ua[i] : ub[i];
            float target = __shfl_sync(0xFFFFFFFFu, src, cur & 31);
            float sa = va[i] + trans_sh[cur * 49 + l];
            bool eq0 = (sa == target);
            bool eq1 = false;
            if (two) {
                float sb = vb[i] + trans_sh[cur * 49 + l + 32];
                eq1 = (sb == target);
            }
            unsigned m0 = __ballot_sync(0xFFFFFFFFu, eq0);
            unsigned m1 = __ballot_sync(0xFFFFFFFFu, eq1);
            cur = m0 ? (__ffs(m0) - 1) : (__ffs(m1) + 31);
        }
        if (c < 63) {
#pragma unroll
            for (int i = 0; i < 8; i++) {
                va[i] = nva[i]; vb[i] = nvb[i];
                ua[i] = nua[i]; ub[i] = nub[i];
            }
        }
    }

    __syncwarp();
    float* dst = out + 2 * BB + (size_t)b * TT;
    for (int t = l; t < TT; t += 32)
        dst[t] = path_sh[w][t];
}

// ============================================================
extern "C" void kernel_launch(void* const* d_in, const int* in_sizes, int n_in,
                              void* d_out, int out_size) {
    const float* feats = (const float*)d_in[0];
    const float* trans = (const float*)d_in[1];
    const int*   tags  = (const int*)d_in[2];
    float* out = (float*)d_out;

    crf_main_kernel<<<BB / NB, MAIN_THREADS>>>(feats, trans, tags, out);
    backtrack_kernel<<<BB / 8, 256>>>(trans, out);
}

// round 12
// speedup vs baseline: 1.5589x; 1.5589x over previous
#include <cuda_runtime.h>
#include <math.h>
#include <float.h>

#define BB 1024
#define TT 512
#define KK 48
#define NEGV (-10000.0f)
#define TAG_START 46
#define TAG_STOP 47
#define NBAT 4                      // batches per CTA (2 groups x 2 batches)
#define MAIN_THREADS 192            // 2 groups x 96 threads

// ---- device scratch (no allocations allowed) ----
__device__ int   g_bestlast[BB];
__device__ float g_v[BB * TT * KK];   // per-step Viterbi value vectors (100 MB)

// f32x2 packed helpers (sm_103a; add/mul/fma only — no packed max exists)
#define F32X2_FMA(d, a, b, c) \
    asm("fma.rn.f32x2 %0, %1, %2, %3;" : "=l"(d) : "l"(a), "l"(b), "l"(c))
#define F32X2_ADD(d, a, b) \
    asm("add.rn.f32x2 %0, %1, %2;" : "=l"(d) : "l"(a), "l"(b))
#define F32X2_UNPACK(lo, hi, x) \
    asm("mov.b64 {%0, %1}, %2;" : "=f"(lo), "=f"(hi) : "l"(x))
#define F32X2_PACK(d, lo, hi) \
    asm("mov.b64 %0, {%1, %2};" : "=l"(d) : "f"(lo), "f"(hi))

// ============================================================
// Fused kernel: forward log-partition + Viterbi max + gold, with
// BATCH-PAIR INTERLEAVING: each 96-thread group (3 aligned warps) owns
// two batches A,B. Per step: store both batches' e/v -> ONE named
// barrier -> compute both. Barrier count halved; two independent
// compute streams per warp hide LDS/MUFU latency.
// Per-batch numerics are bit-identical to the proven R5 kernel.
// tid%96 = nx*2 + h : nx = next tag, h = prev half [24h, 24h+24).
// ============================================================
__global__ void __launch_bounds__(MAIN_THREADS, 2)
crf_main_kernel(const float* __restrict__ feats,
                const float* __restrict__ trans,
                const int* __restrict__ tags,
                float* __restrict__ out) {
    __shared__ float trans_sh[KK * 49];                    // masked, pitch 49
    __shared__ __align__(16) float e_sh[2][2][2][KK];      // [par][grp][ab][KK]
    __shared__ __align__(16) float v_sh[2][2][2][KK];
    __shared__ int tag_sh[NBAT][TT];

    int tid = threadIdx.x;
    int grp = tid / 96;          // group = 3 aligned warps
    int r   = tid - grp * 96;
    int nx  = r >> 1;
    int h   = r & 1;
    int base = h * 24;
    int bA  = blockIdx.x * NBAT + grp * 2;
    int bB  = bA + 1;
    int barid = grp + 1;         // named barrier per group (ids 1..2)

    // masked transitions: trans[next, prev]; never INTO start, never OUT of stop
    for (int i = tid; i < KK * KK; i += MAIN_THREADS) {
        int rr = i / KK, cc = i - rr * KK;
        float tv = trans[i];
        if (rr == TAG_START || cc == TAG_STOP) tv = NEGV;
        trans_sh[rr * 49 + cc] = tv;
    }
    for (int i = tid; i < NBAT * TT; i += MAIN_THREADS)
        ((int*)tag_sh)[i] = tags[(size_t)blockIdx.x * NBAT * TT + i];
    __syncthreads();

    // packed register slices of this next-row (24 prevs -> 12 f32x2); shared by A and B
    unsigned long long Ms2[12], ts2[12];
#pragma unroll
    for (int j = 0; j < 12; j++) {
        float t0 = trans_sh[nx * 49 + base + 2 * j];
        float t1 = trans_sh[nx * 49 + base + 2 * j + 1];
        float M0 = (t0 <= -9000.f) ? 0.f : __expf(t0);
        float M1 = (t1 <= -9000.f) ? 0.f : __expf(t1);
        F32X2_PACK(ts2[j], t0, t1);
        F32X2_PACK(Ms2[j], M0, M1);
    }

    float aA = (nx == TAG_START) ? 0.f : NEGV, aB = aA;
    float vA = aA, vB = aA;
    float mA = 0.f, mB = 0.f;
    float goldA = 0.f, goldB = 0.f;
    int ptA = TAG_START, ptB = TAG_START;

    const float* fpA = feats + (size_t)bA * TT * KK + nx;
    const float* fpB = feats + (size_t)bB * TT * KK + nx;
    float emitA = fpA[0], emitB = fpB[0];
    float* voutA = g_v + (size_t)bA * TT * KK + nx;
    float* voutB = g_v + (size_t)bB * TT * KK + nx;

    for (int t = 0; t < TT; t++) {
        int par = t & 1;
        float emitA_n = (t + 1 < TT) ? fpA[(size_t)(t + 1) * KK] : 0.f;
        float emitB_n = (t + 1 < TT) ? fpB[(size_t)(t + 1) * KK] : 0.f;

        if (h == 0) {
            e_sh[par][grp][0][nx] = __expf(aA - mA);
            v_sh[par][grp][0][nx] = vA;
            voutA[(size_t)t * KK] = vA;
            e_sh[par][grp][1][nx] = __expf(aB - mB);
            v_sh[par][grp][1][nx] = vB;
            voutB[(size_t)t * KK] = vB;
        }
        asm volatile("bar.sync %0, 96;" :: "r"(barid));   // ONE barrier for both

        // gold: one (nx==tag, h==0) thread per batch per step
        int tgA = tag_sh[grp * 2 + 0][t];
        int tgB = tag_sh[grp * 2 + 1][t];
        if (h == 0 && nx == tgA) goldA += emitA + trans_sh[tgA * 49 + ptA];
        if (h == 0 && nx == tgB) goldB += emitB + trans_sh[tgB * 49 + ptB];
        ptA = tgA; ptB = tgB;

        // ---- compute A and B: two independent streams (ILP) ----
        const ulonglong2* epA = (const ulonglong2*)&e_sh[par][grp][0][base];
        const ulonglong2* vpA = (const ulonglong2*)&v_sh[par][grp][0][base];
        const ulonglong2* epB = (const ulonglong2*)&e_sh[par][grp][1][base];
        const ulonglong2* vpB = (const ulonglong2*)&v_sh[par][grp][1][base];
        unsigned long long accA0 = 0ull, accA1 = 0ull, accB0 = 0ull, accB1 = 0ull;
        float bA0 = -FLT_MAX, bA1 = -FLT_MAX, bB0 = -FLT_MAX, bB1 = -FLT_MAX;
#pragma unroll
        for (int j = 0; j < 6; j++) {
            ulonglong2 eA2 = epA[j], vA2 = vpA[j];
            ulonglong2 eB2 = epB[j], vB2 = vpB[j];
            F32X2_FMA(accA0, eA2.x, Ms2[2 * j], accA0);
            F32X2_FMA(accA1, eA2.y, Ms2[2 * j + 1], accA1);
            F32X2_FMA(accB0, eB2.x, Ms2[2 * j], accB0);
            F32X2_FMA(accB1, eB2.y, Ms2[2 * j + 1], accB1);
            unsigned long long sA01, sA23, sB01, sB23;
            F32X2_ADD(sA01, vA2.x, ts2[2 * j]);
            F32X2_ADD(sA23, vA2.y, ts2[2 * j + 1]);
            F32X2_ADD(sB01, vB2.x, ts2[2 * j]);
            F32X2_ADD(sB23, vB2.y, ts2[2 * j + 1]);
            float s0, s1, s2, s3;
            F32X2_UNPACK(s0, s1, sA01);
            F32X2_UNPACK(s2, s3, sA23);
            bA0 = fmaxf(bA0, s0); bA1 = fmaxf(bA1, s1);
            bA0 = fmaxf(bA0, s2); bA1 = fmaxf(bA1, s3);
            F32X2_UNPACK(s0, s1, sB01);
            F32X2_UNPACK(s2, s3, sB23);
            bB0 = fmaxf(bB0, s0); bB1 = fmaxf(bB1, s1);
            bB0 = fmaxf(bB0, s2); bB1 = fmaxf(bB1, s3);
        }
        float x0, x1, x2, x3;
        F32X2_UNPACK(x0, x1, accA0);
        F32X2_UNPACK(x2, x3, accA1);
        float accA = (x0 + x1) + (x2 + x3);
        F32X2_UNPACK(x0, x1, accB0);
        F32X2_UNPACK(x2, x3, accB1);
        float accB = (x0 + x1) + (x2 + x3);
        float bestA = fmaxf(bA0, bA1);
        float bestB = fmaxf(bB0, bB1);
        // partner combine (lane^1, same warp)
        accA += __shfl_xor_sync(0xFFFFFFFFu, accA, 1);
        accB += __shfl_xor_sync(0xFFFFFFFFu, accB, 1);
        bestA = fmaxf(bestA, __shfl_xor_sync(0xFFFFFFFFu, bestA, 1));
        bestB = fmaxf(bestB, __shfl_xor_sync(0xFFFFFFFFu, bestB, 1));

        aA = emitA + mA + __logf(accA);   // -inf on START row: harmless
        aB = emitB + mB + __logf(accB);
        vA = bestA + emitA;
        vB = bestB + emitB;
        emitA = emitA_n;
        emitB = emitB_n;

        if ((t & 3) == 3) {
            // exact rescale: m += log(max e). e_sh[par] still valid: its next
            // overwrite (step t+2's store) is gated behind step t+1's barrier.
            float mxA = -FLT_MAX, mxB = -FLT_MAX;
#pragma unroll
            for (int p0 = 0; p0 < KK; p0 += 4) {
                float4 e4 = *reinterpret_cast<const float4*>(&e_sh[par][grp][0][p0]);
                mxA = fmaxf(mxA, fmaxf(fmaxf(e4.x, e4.y), fmaxf(e4.z, e4.w)));
                float4 f4 = *reinterpret_cast<const float4*>(&e_sh[par][grp][1][p0]);
                mxB = fmaxf(mxB, fmaxf(fmaxf(f4.x, f4.y), fmaxf(f4.z, f4.w)));
            }
            mA = mA + __logf(mxA);
            mB = mB + __logf(mxB);
        } else {
            mA += 12.f;  // safe bound on per-step alpha growth
            mB += 12.f;
        }
    }

    // ---- epilogue: logZ, path_score, best_last, gold reduce (both batches) ----
    asm volatile("bar.sync %0, 96;" :: "r"(barid));
    if (h == 0) {
        float tstop = trans_sh[TAG_STOP * 49 + nx];
        e_sh[0][grp][0][nx] = aA + tstop;
        e_sh[0][grp][1][nx] = aB + tstop;
        v_sh[0][grp][0][nx] = vA + tstop;
        v_sh[0][grp][1][nx] = vB + tstop;
        e_sh[1][grp][0][nx] = goldA;
        e_sh[1][grp][1][nx] = goldB;
    }
    asm volatile("bar.sync %0, 96;" :: "r"(barid));
    if (r == 0) {
#pragma unroll
        for (int ab = 0; ab < 2; ab++) {
            int b = bA + ab;
            float mx = -FLT_MAX;
            for (int k = 0; k < KK; k++) mx = fmaxf(mx, e_sh[0][grp][ab][k]);
            float s = 0.f;
            for (int k = 0; k < KK; k++) s += __expf(e_sh[0][grp][ab][k] - mx);
            float logZ = mx + __logf(s);

            float gsum = 0.f;
            for (int k = 0; k < KK; k++) gsum += e_sh[1][grp][ab][k];
            gsum += trans_sh[TAG_STOP * 49 + tag_sh[grp * 2 + ab][TT - 1]];
            out[b] = logZ - gsum;                      // nll

            float bv = -FLT_MAX;
            int bi = 0;
            for (int k = 0; k < KK; k++) {
                float tv = v_sh[0][grp][ab][k];
                if (tv > bv) { bv = tv; bi = k; }      // first-max
            }
            out[BB + b] = bv;                          // path_score
            g_bestlast[b] = bi;
        }
    }
}

// ============================================================
// Backtrack (R5 proven version): one warp per batch. Recomputes
// bp_t[cur] = first-argmax_p (v_t[p] + trans[cur, p]) along the chosen
// path only. Bit-exact: identical FADD inputs; first-max via
// order-preserving int keys + redux.max + ballot/ffs (lowest index wins).
// v rows prefetched 8-deep (loads are cur-independent).
// ============================================================
__global__ void __launch_bounds__(256)
backtrack_kernel(const float* __restrict__ trans, float* __restrict__ out) {
    __shared__ float trans_sh[KK * 49];
    __shared__ float path_sh[8][TT];

    int tid = threadIdx.x;
    int w = tid >> 5, l = tid & 31;
    int b = blockIdx.x * 8 + w;

    for (int i = tid; i < KK * KK; i += 256) {
        int rr = i / KK, cc = i - rr * KK;
        float tv = trans[i];
        if (rr == TAG_START || cc == TAG_STOP) tv = NEGV;
        trans_sh[rr * 49 + cc] = tv;
    }
    __syncthreads();

    const float* vbase = g_v + (size_t)b * TT * KK;
    bool two = (l < 16);     // lanes 0..15 also own p = l+32

    float ca[8], cb[8], na[8], nb2[8];
#pragma unroll
    for (int i = 0; i < 8; i++) {
        int t = 511 - i;
        ca[i] = __ldg(&vbase[(size_t)t * KK + l]);
        nb2[i] = 0.f;
        cb[i] = two ? __ldg(&vbase[(size_t)t * KK + l + 32]) : 0.f;
    }

    int cur = g_bestlast[b];

    for (int c = 0; c < 64; c++) {
        int tb = 511 - c * 8;
        if (c < 63) {
#pragma unroll
            for (int i = 0; i < 8; i++) {
                int t = tb - 8 - i;
                na[i] = __ldg(&vbase[(size_t)t * KK + l]);
                nb2[i] = two ? __ldg(&vbase[(size_t)t * KK + l + 32]) : 0.f;
            }
        }
#pragma unroll
        for (int i = 0; i < 8; i++) {
            int t = tb - i;
            if (l == 0) path_sh[w][t] = (float)cur;
            // scores for this row
            float sa = ca[i] + trans_sh[cur * 49 + l];
            float sl = sa;
            int pl = l;
            if (two) {
                float sb = cb[i] + trans_sh[cur * 49 + l + 32];
                if (sb > sa) { sl = sb; pl = l + 32; }   // strict: lower idx wins tie
            }
            // order-preserving int key (no NaNs present)
            int u = __float_as_int(sl);
            int key = u ^ ((u >> 31) & 0x7FFFFFFF);
            int bk;
            asm("redux.sync.max.s32 %0, %1, 0xffffffff;" : "=r"(bk) : "r"(key));
            unsigned m0 = __ballot_sync(0xFFFFFFFFu, (key == bk) && (pl < 32));
            unsigned m1 = __ballot_sync(0xFFFFFFFFu, (key == bk));
            cur = m0 ? (__ffs(m0) - 1) : (__ffs(m1) - 1 + 32);
        }
        if (c < 63) {
#pragma unroll
            for (int i = 0; i < 8; i++) { ca[i] = na[i]; cb[i] = nb2[i]; }
        }
    }

    __syncwarp();
    float* dst = out + 2 * BB + (size_t)b * TT;
    for (int t = l; t < TT; t += 32)
        dst[t] = path_sh[w][t];
}

// ============================================================
extern "C" void kernel_launch(void* const* d_in, const int* in_sizes, int n_in,
                              void* d_out, int out_size) {
    const float* feats = (const float*)d_in[0];
    const float* trans = (const float*)d_in[1];
    const int*   tags  = (const int*)d_in[2];
    float* out = (float*)d_out;

    crf_main_kernel<<<BB / NBAT, MAIN_THREADS>>>(feats, trans, tags, out);
    backtrack_kernel<<<BB / 8, 256>>>(trans, out);
}